// round 14
// baseline (speedup 1.0000x reference)
#include <cuda_runtime.h>

// 2-layer LSTM, B=2048 T=2048 H1=36 H2=1, fp32.
// R13: j-SPLIT across 2 warps, 2 seqs/block, grid 1024 x 64thr -> 2048 warps
//      (13.8/SM, 2x residency of R11). Symmetric roles, no idle phases:
//   warp0: j in [0,18) + seq A acts/L2;  warp1: j in [18,36) + seq B.
//   Per step: jloop(half, both seqs) -> STS partials -> bar -> combine ->
//             L2(t-1, own seq) -> acts(own seq) -> bar.
//   x/bias terms live only in warp0's weights (warp1 zeroed) => combine = add.
//   Sigmoid 0.5-fold kept (exact). __syncthreads drains STS (HW-native).

#define FULLMASK 0xffffffffu
#define H1C 36
#define JH  18
#define TT 2048

__device__ __forceinline__ float2 ffma2(float2 a, float2 b, float2 c) {
    float2 d;
    asm("fma.rn.f32x2 %0, %1, %2, %3;"
        : "=l"(reinterpret_cast<unsigned long long&>(d))
        : "l"(reinterpret_cast<unsigned long long&>(a)),
          "l"(reinterpret_cast<unsigned long long&>(b)),
          "l"(reinterpret_cast<unsigned long long&>(c)));
    return d;
}
__device__ __forceinline__ float2 fadd2(float2 a, float2 b) {
    float2 d;
    asm("add.rn.f32x2 %0, %1, %2;"
        : "=l"(reinterpret_cast<unsigned long long&>(d))
        : "l"(reinterpret_cast<unsigned long long&>(a)),
          "l"(reinterpret_cast<unsigned long long&>(b)));
    return d;
}
__device__ __forceinline__ float tanha(float x) {
    float y;
    asm("tanh.approx.f32 %0, %1;" : "=f"(y) : "f"(x));
    return y;
}

struct Smem {
    float4 hd4[40];    // (hA, hA, hB, hB) per unit; [36..39] pad = 0
    float2 hr[40];     // (relu hA, relu hB); [36..39] pad = 0
    float4 p4[2][32];  // partial (g01.x, g01.y, g23.x, g23.y); [0]=seqA (by w1), [1]=seqB (by w0)
    float  p1[2][32];  // partial extra-slot
};

__global__ void __launch_bounds__(64, 7)
lstm2_kernel(const float* __restrict__ x,
             const float* __restrict__ W_ih1, const float* __restrict__ W_hh1,
             const float* __restrict__ b_ih1, const float* __restrict__ b_hh1,
             const float* __restrict__ W_ih2, const float* __restrict__ W_hh2,
             const float* __restrict__ b_ih2, const float* __restrict__ b_hh2,
             float* __restrict__ out)
{
    __shared__ Smem sm;
    const int tid  = threadIdx.x;
    const int warp = tid >> 5;          // 0: j 0..17, seq A   1: j 18..35, seq B
    const int lane = tid & 31;
    const int jb   = warp * JH;
    const int seqA = blockIdx.x * 2;
    const float winit = warp ? 0.0f : 1.0f;   // x/bias only in warp0's partials

    // ---- main slots: (i,f,g,o) of unit = lane; sigmoid rows pre-scaled 0.5
    const int r0 = lane, r1 = H1C + lane, r2 = 2 * H1C + lane, r3 = 3 * H1C + lane;
    float2 Wp01[JH], Wp23[JH];
    #pragma unroll
    for (int k = 0; k < JH; ++k) {
        const int j = jb + k;
        Wp01[k] = make_float2(0.5f * W_hh1[r0 * H1C + j], 0.5f * W_hh1[r1 * H1C + j]);
        Wp23[k] = make_float2(W_hh1[r2 * H1C + j], 0.5f * W_hh1[r3 * H1C + j]);
    }
    const float2 wih01 = make_float2(winit * 0.5f * W_ih1[r0], winit * 0.5f * W_ih1[r1]);
    const float2 wih23 = make_float2(winit * W_ih1[r2], winit * 0.5f * W_ih1[r3]);
    const float2 bs01  = make_float2(winit * 0.5f * (b_ih1[r0] + b_hh1[r0]),
                                     winit * 0.5f * (b_ih1[r1] + b_hh1[r1]));
    const float2 bs23  = make_float2(winit * (b_ih1[r2] + b_hh1[r2]),
                                     winit * 0.5f * (b_ih1[r3] + b_hh1[r3]));

    // ---- extra units 32..35: lane<16 -> gate (lane>>2) of unit 32+(lane&3)
    const bool eok = lane < 16;
    const int  gEx = lane >> 2;
    const int  u   = lane & 3;
    const float esO = (gEx == 2) ? 1.0f : 0.5f;
    const float eoO = (gEx == 2) ? 0.0f : 0.5f;
    const int  r4  = eok ? (gEx * H1C + 32 + u) : 0;
    const float esW = (gEx == 2) ? 1.0f : 0.5f;
    float W4[JH];
    #pragma unroll
    for (int k = 0; k < JH; ++k)
        W4[k] = eok ? (esW * W_hh1[r4 * H1C + jb + k]) : 0.0f;
    const float wih4 = eok ? (winit * esW * W_ih1[r4]) : 0.0f;
    const float bs4  = eok ? (winit * esW * (b_ih1[r4] + b_hh1[r4])) : 0.0f;

    // ---- L2 (own seq): lane handles gate q over j = j0 + 8m; asc folded
    const int q  = lane & 3;
    const int j0 = lane >> 2;
    const float asc = (q == 2) ? 1.0f : 0.5f;
    const float aoc = (q == 2) ? 0.0f : 0.5f;
    float w2r[4];
    #pragma unroll
    for (int m = 0; m < 4; ++m)
        w2r[m] = asc * W_ih2[q * H1C + j0 + 8 * m];
    const float w2x = (j0 < 4) ? asc * W_ih2[q * H1C + 32 + j0] : 0.0f;
    const float b2q = asc * (b_ih2[q] + b_hh2[q]);
    const float whq = asc * W_hh2[q];

    // smem init
    if (tid < 40) {
        sm.hd4[tid] = make_float4(0.f, 0.f, 0.f, 0.f);
        sm.hr[tid]  = make_float2(0.f, 0.f);
    }
    __syncthreads();

    const float* xA = x   + (size_t)seqA * TT;
    const float* xB = xA + TT;
    float* oOwn = out + (size_t)(seqA + warp) * TT;   // warp0 -> seqA, warp1 -> seqB

    float c1 = 0.f, cE = 0.f;            // own-seq L1 cell states (main + extra)
    float l2c = 0.f, l2h = 0.f, ob = 0.f;
    float xcA = xA[lane], xcB = xB[lane];

    float2 accA01, accA23, accB01, accB23;
    float  accA4, accB4;
    float2 m01, m23;                     // combined own-seq gates
    float  m4;

    // ---- L1 half-j accumulation for step t (reads hd4(t-1)), both seqs
    auto jloop = [&](float xa, float xb) {
        accA01 = ffma2(make_float2(xa, xa), wih01, bs01);
        accA23 = ffma2(make_float2(xa, xa), wih23, bs23);
        accB01 = ffma2(make_float2(xb, xb), wih01, bs01);
        accB23 = ffma2(make_float2(xb, xb), wih23, bs23);
        accA4  = fmaf(xa, wih4, bs4);
        accB4  = fmaf(xb, wih4, bs4);
        #pragma unroll
        for (int k = 0; k < JH; ++k) {
            const float4 h4 = sm.hd4[jb + k];
            const float2 hA2 = make_float2(h4.x, h4.y);
            const float2 hB2 = make_float2(h4.z, h4.w);
            accA01 = ffma2(Wp01[k], hA2, accA01);
            accA23 = ffma2(Wp23[k], hA2, accA23);
            accB01 = ffma2(Wp01[k], hB2, accB01);
            accB23 = ffma2(Wp23[k], hB2, accB23);
            accA4  = fmaf(W4[k], h4.x, accA4);
            accB4  = fmaf(W4[k], h4.z, accB4);
        }
    };

    // ---- exchange partials + combine own-seq gates (contains bar1)
    auto exchange = [&]() {
        const float2 o01 = warp ? accA01 : accB01;   // other-seq partial out
        const float2 o23 = warp ? accA23 : accB23;
        sm.p4[1 - warp][lane] = make_float4(o01.x, o01.y, o23.x, o23.y);
        sm.p1[1 - warp][lane] = warp ? accA4 : accB4;
        __syncthreads();                             // bar1 (drains STS)
        const float4 r4v = sm.p4[warp][lane];        // own-seq partial from peer
        const float  r1v = sm.p1[warp][lane];
        m01 = fadd2(warp ? accB01 : accA01, make_float2(r4v.x, r4v.y));
        m23 = fadd2(warp ? accB23 : accA23, make_float2(r4v.z, r4v.w));
        m4  = (warp ? accB4 : accA4) + r1v;
    };

    // ---- L2 for step t-1, own seq (reads own component of hr(t-1))
    auto l2step = [&](int tpmod) {
        const int off = warp << 2;
        float sS = 0.f;
        #pragma unroll
        for (int m = 0; m < 4; ++m) {
            const float hv = *(const float*)((const char*)&sm.hr[j0 + 8 * m] + off);
            sS = fmaf(w2r[m], hv, sS);
        }
        const float hx = *(const float*)((const char*)&sm.hr[32 + j0] + off);
        sS = fmaf(w2x, hx, sS);
        #pragma unroll
        for (int o = 4; o <= 16; o <<= 1)
            sS += __shfl_xor_sync(FULLMASK, sS, o);
        const float v   = fmaf(whq, l2h, sS + b2q);
        const float act = fmaf(asc, tanha(v), aoc);
        const int base = lane & ~3;
        const float iV = __shfl_sync(FULLMASK, act, base + 0);
        const float fV = __shfl_sync(FULLMASK, act, base + 1);
        const float gV = __shfl_sync(FULLMASK, act, base + 2);
        const float oV = __shfl_sync(FULLMASK, act, base + 3);
        l2c = fmaf(fV, l2c, iV * gV);
        l2h = oV * tanha(l2c);
        ob = (tpmod == lane) ? l2h : ob;
    };

    // ---- own-seq activations for step t (writes own halves of hd4/hr; bar2)
    auto acts = [&]() {
        {
            const float iV = fmaf(0.5f, tanha(m01.x), 0.5f);
            const float fV = fmaf(0.5f, tanha(m01.y), 0.5f);
            const float gV = tanha(m23.x);
            const float oV = fmaf(0.5f, tanha(m23.y), 0.5f);
            c1 = fmaf(fV, c1, iV * gV);
            const float h = oV * tanha(c1);
            *(float2*)((char*)&sm.hd4[lane] + (warp << 3)) = make_float2(h, h);
            *(float*)((char*)&sm.hr[lane] + (warp << 2))   = fmaxf(h, 0.f);
        }
        {   // extra units 32..35 (own seq)
            const float eAct = fmaf(esO, tanha(m4), eoO);
            const float iE = __shfl_sync(FULLMASK, eAct, u);
            const float fE = __shfl_sync(FULLMASK, eAct, u + 4);
            const float gV = __shfl_sync(FULLMASK, eAct, u + 8);
            const float oE = __shfl_sync(FULLMASK, eAct, u + 12);
            cE = fmaf(fE, cE, iE * gV);
            const float hE = oE * tanha(cE);
            if (lane < 4) {
                *(float2*)((char*)&sm.hd4[32 + u] + (warp << 3)) = make_float2(hE, hE);
                *(float*)((char*)&sm.hr[32 + u] + (warp << 2))   = fmaxf(hE, 0.f);
            }
        }
        __syncthreads();   // bar2: hd4(t)/hr(t) complete before next jloop
    };

    // ---- peel step 0 (hd4 = 0; no L2 yet)
    jloop(__shfl_sync(FULLMASK, xcA, 0), __shfl_sync(FULLMASK, xcB, 0));
    exchange();
    acts();

    // ---- main: tb = 0..62 (inner st = 1..31, then first step of next chunk)
    for (int tb = 0; tb < 63; ++tb) {
        const float xnA = xA[(tb + 1) * 32 + lane];
        const float xnB = xB[(tb + 1) * 32 + lane];

        #pragma unroll 1
        for (int st = 1; st < 32; ++st) {
            const float xa = __shfl_sync(FULLMASK, xcA, st);
            const float xb = __shfl_sync(FULLMASK, xcB, st);
            jloop(xa, xb);
            exchange();
            l2step(st - 1);
            acts();
        }
        {   // first step of next chunk; its L2 closes this chunk
            const float xa = __shfl_sync(FULLMASK, xnA, 0);
            const float xb = __shfl_sync(FULLMASK, xnB, 0);
            jloop(xa, xb);
            exchange();
            l2step(31);
            acts();
        }
        oOwn[tb * 32 + lane] = ob;
        xcA = xnA;
        xcB = xnB;
    }

    // ---- last block (tb = 63): bodies t = 2017..2047, final L2 for 2047
    #pragma unroll 1
    for (int st = 1; st < 32; ++st) {
        const float xa = __shfl_sync(FULLMASK, xcA, st);
        const float xb = __shfl_sync(FULLMASK, xcB, st);
        jloop(xa, xb);
        exchange();
        l2step(st - 1);
        acts();
    }
    l2step(31);
    oOwn[63 * 32 + lane] = ob;
}

extern "C" void kernel_launch(void* const* d_in, const int* in_sizes, int n_in,
                              void* d_out, int out_size)
{
    const float* x     = (const float*)d_in[0];
    const float* W_ih1 = (const float*)d_in[1];
    const float* W_hh1 = (const float*)d_in[2];
    const float* b_ih1 = (const float*)d_in[3];
    const float* b_hh1 = (const float*)d_in[4];
    const float* W_ih2 = (const float*)d_in[5];
    const float* W_hh2 = (const float*)d_in[6];
    const float* b_ih2 = (const float*)d_in[7];
    const float* b_hh2 = (const float*)d_in[8];

    const int B = in_sizes[0] / TT;   // x is [B, T, 1]
    lstm2_kernel<<<B / 2, 64>>>(x, W_ih1, W_hh1, b_ih1, b_hh1,
                                W_ih2, W_hh2, b_ih2, b_hh2,
                                (float*)d_out);
}

// round 15
// speedup vs baseline: 1.4894x; 1.4894x over previous
#include <cuda_runtime.h>

// 2-layer LSTM, B=2048 T=2048 H1=36 H2=1, fp32.
// R14: PHASE-SPLIT. L2 never feeds L1, so per 32-step chunk:
//   phase 1: L1 only (jloop + acts), hr logged to transposed bank-padded bufs
//   phase 2: L2 dots for all 32 steps (parallel, lane = t, zero shuffles)
//   phase 3: L2 recurrence, 32 serial iters, all lanes redundant (broadcast)
// 1 warp / 2 seqs, 1024 blocks; reg W; hd4 LDS.128; sigmoid 0.5-fold; no peels.

#define FULLMASK 0xffffffffu
#define H1C 36
#define TT 2048

__device__ __forceinline__ float2 ffma2(float2 a, float2 b, float2 c) {
    float2 d;
    asm("fma.rn.f32x2 %0, %1, %2, %3;"
        : "=l"(reinterpret_cast<unsigned long long&>(d))
        : "l"(reinterpret_cast<unsigned long long&>(a)),
          "l"(reinterpret_cast<unsigned long long&>(b)),
          "l"(reinterpret_cast<unsigned long long&>(c)));
    return d;
}
__device__ __forceinline__ float tanha(float x) {
    float y;
    asm("tanh.approx.f32 %0, %1;" : "=f"(y) : "f"(x));
    return y;
}

struct Smem {
    float4 hd4[40];       // (hA, hA, hB, hB) per unit; [36..39] pad = 0
    float  hrA[36][33];   // relu(hA) per unit x step (33: bank-safe)
    float  hrB[36][33];
    float4 w4s[36];       // (0.5wi, 0.5wf, wg, 0.5wo) per unit (asc folded)
    float4 dotsA[32];     // per-step L2 gate dots, seq A
    float4 dotsB[32];
};

__global__ void __launch_bounds__(32)
lstm2_kernel(const float* __restrict__ x,
             const float* __restrict__ W_ih1, const float* __restrict__ W_hh1,
             const float* __restrict__ b_ih1, const float* __restrict__ b_hh1,
             const float* __restrict__ W_ih2, const float* __restrict__ W_hh2,
             const float* __restrict__ b_ih2, const float* __restrict__ b_hh2,
             float* __restrict__ out)
{
    __shared__ Smem sm;
    const int lane = threadIdx.x;
    const int seqA = blockIdx.x * 2;

    // ---- main slots: (i,f,g,o) of unit = lane; sigmoid rows pre-scaled 0.5
    const int r0 = lane, r1 = H1C + lane, r2 = 2 * H1C + lane, r3 = 3 * H1C + lane;
    float2 Wp01[H1C], Wp23[H1C];
    #pragma unroll
    for (int j = 0; j < H1C; ++j) {
        Wp01[j] = make_float2(0.5f * W_hh1[r0 * H1C + j], 0.5f * W_hh1[r1 * H1C + j]);
        Wp23[j] = make_float2(W_hh1[r2 * H1C + j], 0.5f * W_hh1[r3 * H1C + j]);
    }
    const float2 wih01 = make_float2(0.5f * W_ih1[r0], 0.5f * W_ih1[r1]);
    const float2 wih23 = make_float2(W_ih1[r2], 0.5f * W_ih1[r3]);
    const float2 bs01  = make_float2(0.5f * (b_ih1[r0] + b_hh1[r0]),
                                     0.5f * (b_ih1[r1] + b_hh1[r1]));
    const float2 bs23  = make_float2(b_ih1[r2] + b_hh1[r2],
                                     0.5f * (b_ih1[r3] + b_hh1[r3]));

    // ---- extra units 32..35: lane<16 -> gate (lane>>2) of unit 32+(lane&3)
    const bool eok = lane < 16;
    const int  gE  = lane >> 2;
    const int  u   = lane & 3;
    const float esO = (gE == 2) ? 1.0f : 0.5f;
    const float eoO = (gE == 2) ? 0.0f : 0.5f;
    const int  r4  = eok ? (gE * H1C + 32 + u) : 0;
    const float esW = (gE == 2) ? 1.0f : 0.5f;
    float W4[H1C];
    #pragma unroll
    for (int j = 0; j < H1C; ++j)
        W4[j] = eok ? (esW * W_hh1[r4 * H1C + j]) : 0.0f;
    const float wih4 = eok ? (esW * W_ih1[r4]) : 0.0f;
    const float bs4  = eok ? (esW * (b_ih1[r4] + b_hh1[r4])) : 0.0f;

    // ---- L2 constants (asc = 0.5 for sigmoid gates folded everywhere)
    const float b2i = 0.5f * (b_ih2[0] + b_hh2[0]);
    const float b2f = 0.5f * (b_ih2[1] + b_hh2[1]);
    const float b2g =        (b_ih2[2] + b_hh2[2]);
    const float b2o = 0.5f * (b_ih2[3] + b_hh2[3]);
    const float whI = 0.5f * W_hh2[0];
    const float whF = 0.5f * W_hh2[1];
    const float whG =        W_hh2[2];
    const float whO = 0.5f * W_hh2[3];

    // smem init
    for (int i = lane; i < H1C; i += 32)
        sm.w4s[i] = make_float4(0.5f * W_ih2[0 * H1C + i], 0.5f * W_ih2[1 * H1C + i],
                                W_ih2[2 * H1C + i], 0.5f * W_ih2[3 * H1C + i]);
    if (lane < 20) {
        sm.hd4[2 * lane]     = make_float4(0.f, 0.f, 0.f, 0.f);
        sm.hd4[2 * lane + 1] = make_float4(0.f, 0.f, 0.f, 0.f);
    }
    __syncthreads();

    const float* xA = x   + (size_t)seqA * TT;
    const float* xB = xA + TT;
    float*       oA = out + (size_t)seqA * TT;
    float*       oB = oA + TT;

    float cA = 0.f, cB = 0.f, cEA = 0.f, cEB = 0.f;
    float l2cA = 0.f, l2cB = 0.f, l2hA = 0.f, l2hB = 0.f;
    float obA = 0.f, obB = 0.f;

    float2 aA01, aA23, aB01, aB23;
    float  aA4, aB4;

    // ---- L1 gate accumulation for step t (reads hd4(t-1))
    auto jloop = [&](float xa, float xb) {
        aA01 = ffma2(make_float2(xa, xa), wih01, bs01);
        aA23 = ffma2(make_float2(xa, xa), wih23, bs23);
        aB01 = ffma2(make_float2(xb, xb), wih01, bs01);
        aB23 = ffma2(make_float2(xb, xb), wih23, bs23);
        aA4  = fmaf(xa, wih4, bs4);
        aB4  = fmaf(xb, wih4, bs4);
        #pragma unroll
        for (int j = 0; j < H1C; ++j) {
            const float4 h4 = sm.hd4[j];
            const float2 hA2 = make_float2(h4.x, h4.y);
            const float2 hB2 = make_float2(h4.z, h4.w);
            aA01 = ffma2(Wp01[j], hA2, aA01);
            aA23 = ffma2(Wp23[j], hA2, aA23);
            aB01 = ffma2(Wp01[j], hB2, aB01);
            aB23 = ffma2(Wp23[j], hB2, aB23);
            aA4  = fmaf(W4[j], h4.x, aA4);
            aB4  = fmaf(W4[j], h4.z, aB4);
        }
    };

    // ---- L1 activations for step t; logs hr into transposed buffers
    auto acts = [&](int tm) {
        {
            const float iA = fmaf(0.5f, tanha(aA01.x), 0.5f);
            const float fA = fmaf(0.5f, tanha(aA01.y), 0.5f);
            const float gA = tanha(aA23.x);
            const float oAa = fmaf(0.5f, tanha(aA23.y), 0.5f);
            cA = fmaf(fA, cA, iA * gA);
            const float hA = oAa * tanha(cA);
            const float iB = fmaf(0.5f, tanha(aB01.x), 0.5f);
            const float fB = fmaf(0.5f, tanha(aB01.y), 0.5f);
            const float gB = tanha(aB23.x);
            const float oBa = fmaf(0.5f, tanha(aB23.y), 0.5f);
            cB = fmaf(fB, cB, iB * gB);
            const float hB = oBa * tanha(cB);
            sm.hd4[lane]      = make_float4(hA, hA, hB, hB);
            sm.hrA[lane][tm]  = fmaxf(hA, 0.f);
            sm.hrB[lane][tm]  = fmaxf(hB, 0.f);
        }
        {   // extra units 32..35
            const float eAv = fmaf(esO, tanha(aA4), eoO);
            const float eBv = fmaf(esO, tanha(aB4), eoO);
            const float iA = __shfl_sync(FULLMASK, eAv, u);
            const float fA = __shfl_sync(FULLMASK, eAv, u + 4);
            const float gA = __shfl_sync(FULLMASK, eAv, u + 8);
            const float oAe = __shfl_sync(FULLMASK, eAv, u + 12);
            const float iB = __shfl_sync(FULLMASK, eBv, u);
            const float fB = __shfl_sync(FULLMASK, eBv, u + 4);
            const float gB = __shfl_sync(FULLMASK, eBv, u + 8);
            const float oBe = __shfl_sync(FULLMASK, eBv, u + 12);
            cEA = fmaf(fA, cEA, iA * gA);
            cEB = fmaf(fB, cEB, iB * gB);
            const float hEA = oAe * tanha(cEA);
            const float hEB = oBe * tanha(cEB);
            if (lane < 4) {
                sm.hd4[32 + u]     = make_float4(hEA, hEA, hEB, hEB);
                sm.hrA[32 + u][tm] = fmaxf(hEA, 0.f);
                sm.hrB[32 + u][tm] = fmaxf(hEB, 0.f);
            }
        }
        __syncwarp();   // STS (hd4 + hr logs) ordered before later LDS
    };

    float xcA = xA[lane];
    float xcB = xB[lane];

    for (int tb = 0; tb < 64; ++tb) {
        const int nb = (tb < 63) ? tb + 1 : 63;       // dup load at end (in-bounds)
        const float xnA = xA[nb * 32 + lane];
        const float xnB = xB[nb * 32 + lane];

        // ---- phase 1: L1 for steps tb*32 .. tb*32+31
        #pragma unroll 1
        for (int st = 0; st < 32; ++st) {
            const float xa = __shfl_sync(FULLMASK, xcA, st);
            const float xb = __shfl_sync(FULLMASK, xcB, st);
            jloop(xa, xb);
            acts(st);
        }

        // ---- phase 2: L2 gate dots for all 32 steps (lane = t)
        {
            float aIA = b2i, aFA = b2f, aGA = b2g, aOA = b2o;
            float aIB = b2i, aFB = b2f, aGB = b2g, aOB = b2o;
            #pragma unroll
            for (int j = 0; j < H1C; ++j) {
                const float4 wv = sm.w4s[j];              // broadcast
                const float hA = sm.hrA[j][lane];         // bank (j+lane)%32
                const float hB = sm.hrB[j][lane];
                aIA = fmaf(wv.x, hA, aIA);
                aFA = fmaf(wv.y, hA, aFA);
                aGA = fmaf(wv.z, hA, aGA);
                aOA = fmaf(wv.w, hA, aOA);
                aIB = fmaf(wv.x, hB, aIB);
                aFB = fmaf(wv.y, hB, aFB);
                aGB = fmaf(wv.z, hB, aGB);
                aOB = fmaf(wv.w, hB, aOB);
            }
            sm.dotsA[lane] = make_float4(aIA, aFA, aGA, aOA);
            sm.dotsB[lane] = make_float4(aIB, aFB, aGB, aOB);
            __syncwarp();
        }

        // ---- phase 3: L2 recurrence, 32 serial steps (all lanes redundant)
        #pragma unroll 1
        for (int t2 = 0; t2 < 32; ++t2) {
            const float4 dA = sm.dotsA[t2];               // broadcast
            const float4 dB = sm.dotsB[t2];
            {
                const float vI = fmaf(whI, l2hA, dA.x);
                const float vF = fmaf(whF, l2hA, dA.y);
                const float vG = fmaf(whG, l2hA, dA.z);
                const float vO = fmaf(whO, l2hA, dA.w);
                const float iV = fmaf(0.5f, tanha(vI), 0.5f);
                const float fV = fmaf(0.5f, tanha(vF), 0.5f);
                const float gV = tanha(vG);
                const float oV = fmaf(0.5f, tanha(vO), 0.5f);
                l2cA = fmaf(fV, l2cA, iV * gV);
                l2hA = oV * tanha(l2cA);
                obA = (t2 == lane) ? l2hA : obA;
            }
            {
                const float vI = fmaf(whI, l2hB, dB.x);
                const float vF = fmaf(whF, l2hB, dB.y);
                const float vG = fmaf(whG, l2hB, dB.z);
                const float vO = fmaf(whO, l2hB, dB.w);
                const float iV = fmaf(0.5f, tanha(vI), 0.5f);
                const float fV = fmaf(0.5f, tanha(vF), 0.5f);
                const float gV = tanha(vG);
                const float oV = fmaf(0.5f, tanha(vO), 0.5f);
                l2cB = fmaf(fV, l2cB, iV * gV);
                l2hB = oV * tanha(l2cB);
                obB = (t2 == lane) ? l2hB : obB;
            }
        }

        oA[tb * 32 + lane] = obA;     // coalesced chunk flush
        oB[tb * 32 + lane] = obB;
        xcA = xnA;
        xcB = xnB;
    }
}

extern "C" void kernel_launch(void* const* d_in, const int* in_sizes, int n_in,
                              void* d_out, int out_size)
{
    const float* x     = (const float*)d_in[0];
    const float* W_ih1 = (const float*)d_in[1];
    const float* W_hh1 = (const float*)d_in[2];
    const float* b_ih1 = (const float*)d_in[3];
    const float* b_hh1 = (const float*)d_in[4];
    const float* W_ih2 = (const float*)d_in[5];
    const float* W_hh2 = (const float*)d_in[6];
    const float* b_ih2 = (const float*)d_in[7];
    const float* b_hh2 = (const float*)d_in[8];

    const int B = in_sizes[0] / TT;   // x is [B, T, 1]
    lstm2_kernel<<<B / 2, 32>>>(x, W_ih1, W_hh1, b_ih1, b_hh1,
                                W_ih2, W_hh2, b_ih2, b_hh2,
                                (float*)d_out);
}